// round 7
// baseline (speedup 1.0000x reference)
#include <cuda_runtime.h>
#include <cuda_bf16.h>
#include <stdint.h>

#define BATCH   8
#define NNODE   1024
#define CH      256
#define NEDGE   16384
#define BIGN    (BATCH * NNODE)          // 8192
#define WPR     32                       // bitmap words per row
#define CSRW    48                       // padded CSR width per row (ints)

// ---- scratch (__device__ globals; allocation-free rule) ----
__device__ __align__(128) unsigned      g_adj[BIGN * WPR];    // 1 MB adjacency bitmap
__device__ __align__(128) float         g_dinv[BIGN];
__device__ __align__(128) float         g_ys[BIGN * CH];      // ys = dinv * (x @ W^T)
__device__ __align__(128) int           g_csr[BIGN * CSRW];
__device__ __align__(128) int           g_cnt[BIGN];
__device__ __align__(128) __nv_bfloat16 g_xhi[BIGN * CH];     // x split hi (4 MB)
__device__ __align__(128) __nv_bfloat16 g_xlo[BIGN * CH];     // x split lo (4 MB)
__device__ __align__(128) __nv_bfloat16 g_whi[CH * CH];
__device__ __align__(128) __nv_bfloat16 g_wlo[CH * CH];

// ================================================================ helpers
__device__ __forceinline__ uint32_t s2u(const void* p) {
    uint32_t a;
    asm("{ .reg .u64 t; cvta.to.shared.u64 t, %1; cvt.u32.u64 %0, t; }" : "=r"(a) : "l"(p));
    return a;
}
__device__ __forceinline__ void split2(float2 f, uint32_t& hi, uint32_t& lo) {
    asm("cvt.rn.bf16x2.f32 %0, %1, %2;" : "=r"(hi) : "f"(f.y), "f"(f.x));
    float hx = __uint_as_float(hi << 16);
    float hy = __uint_as_float(hi & 0xffff0000u);
    asm("cvt.rn.bf16x2.f32 %0, %1, %2;" : "=r"(lo) : "f"(f.y - hy), "f"(f.x - hx));
}
__device__ __forceinline__ void mma16816(float* c, const uint32_t* a, const uint32_t* b) {
    asm volatile(
        "mma.sync.aligned.m16n8k16.row.col.f32.bf16.bf16.f32 "
        "{%0,%1,%2,%3}, {%4,%5,%6,%7}, {%8,%9}, {%0,%1,%2,%3};"
        : "+f"(c[0]), "+f"(c[1]), "+f"(c[2]), "+f"(c[3])
        : "r"(a[0]), "r"(a[1]), "r"(a[2]), "r"(a[3]), "r"(b[0]), "r"(b[1]));
}
__device__ __forceinline__ void ldsm4(uint32_t* r, uint32_t addr) {
    asm volatile("ldmatrix.sync.aligned.m8n8.x4.shared.b16 {%0,%1,%2,%3}, [%4];"
                 : "=r"(r[0]), "=r"(r[1]), "=r"(r[2]), "=r"(r[3]) : "r"(addr));
}
__device__ __forceinline__ void cpasync16(uint32_t dst, const void* src) {
    asm volatile("{ .reg .u64 g; cvta.to.global.u64 g, %1;\n\t"
                 "cp.async.cg.shared.global [%0], [g], 16; }"
                 :: "r"(dst), "l"(src) : "memory");
}

// ================================================================ prep: split x,W to bf16 hi/lo + zero bitmap
__global__ void __launch_bounds__(256) k_prep(const float* __restrict__ x,
                                              const float* __restrict__ Wm)
{
    int t = blockIdx.x * 256 + threadIdx.x;        // 524288 threads, one float4 of x each
    float4 v = ((const float4*)x)[t];
    uint32_t h0, l0, h1, l1;
    split2(make_float2(v.x, v.y), h0, l0);
    split2(make_float2(v.z, v.w), h1, l1);
    ((uint2*)g_xhi)[t] = make_uint2(h0, h1);
    ((uint2*)g_xlo)[t] = make_uint2(l0, l1);
    if (t < CH * CH / 4) {
        float4 w = ((const float4*)Wm)[t];
        split2(make_float2(w.x, w.y), h0, l0);
        split2(make_float2(w.z, w.w), h1, l1);
        ((uint2*)g_whi)[t] = make_uint2(h0, h1);
        ((uint2*)g_wlo)[t] = make_uint2(l0, l1);
    }
    if (t < BIGN * WPR / 4)
        ((uint4*)g_adj)[t] = make_uint4(0u, 0u, 0u, 0u);
}

// ================================================================ edge scatter (dedup via bitmap)
__global__ void k_scatter(const int* __restrict__ ei) {
    int t = blockIdx.x * blockDim.x + threadIdx.x;
    if (t >= NEDGE * BATCH) return;
    int src = ei[t];
    int dst = ei[NEDGE * BATCH + t];
    int b   = t & (BATCH - 1);
    int row = b * NNODE + src;
    atomicOr(&g_adj[row * WPR + (dst >> 5)], 1u << (dst & 31));
}

// ================================================================ degree -> dinv + CSR extraction
__global__ void __launch_bounds__(256) k_deg() {
    int tid  = threadIdx.x;
    int lane = tid & 31;
    int r    = blockIdx.x * 8 + (tid >> 5);

    unsigned w = g_adj[r * WPR + lane];
    int c = __popc(w);
    int s = c;
    #pragma unroll
    for (int o = 1; o < 32; o <<= 1) {
        int v = __shfl_up_sync(0xffffffffu, s, o);
        if (lane >= o) s += v;
    }
    int excl  = s - c;
    int total = __shfl_sync(0xffffffffu, s, 31);
    if (lane == 0) {
        g_dinv[r] = rsqrtf((float)(total + 1));    // +1 self loop (eye)
        g_cnt[r]  = total;
    }
    int i = 0;
    while (w) {
        int b = __ffs(w) - 1;
        w &= w - 1;
        if (excl + i < CSRW) g_csr[r * CSRW + excl + i] = lane * 32 + b;
        i++;
    }
}

// ================================================================ pipelined HMMA GEMM: ys = dinv * (x @ W^T)
// CTA 128x128, 512 threads (16 warps, 4x4), warp tile 32x32,
// K chunks of 64, cp.async double-buffer, ldmatrix fragments.
#define RS    144                     // padded smem row stride (bytes) for 64 bf16
#define TILEB (128 * RS)              // 18432 B per tile
#define BUFB  (4 * TILEB)             // Ahi, Alo, Bhi, Blo
#define GSM   (2 * BUFB)              // 147456 B

__device__ __forceinline__ void load_chunk(uint32_t base, int c, int m0, int n0, int tid) {
    #pragma unroll
    for (int it = 0; it < 2; it++) {
        int idx = tid + it * 512;          // 0..1023
        int row = idx >> 3, seg = idx & 7;
        int ga = (m0 + row) * CH + c * 64 + seg * 8;
        int gb = (n0 + row) * CH + c * 64 + seg * 8;
        uint32_t so = (uint32_t)(row * RS + seg * 16);
        cpasync16(base + so,             &g_xhi[ga]);
        cpasync16(base + TILEB + so,     &g_xlo[ga]);
        cpasync16(base + 2 * TILEB + so, &g_whi[gb]);
        cpasync16(base + 3 * TILEB + so, &g_wlo[gb]);
    }
    asm volatile("cp.async.commit_group;" ::: "memory");
}

__global__ void __launch_bounds__(512) k_gemm()
{
    extern __shared__ __align__(128) char dsm[];
    uint32_t base = s2u(dsm);

    int tid = threadIdx.x;
    int wid = tid >> 5, lane = tid & 31;
    int g = lane >> 2, tg = lane & 3;
    int wm = wid >> 2, wn = wid & 3;           // 4 x 4 warp grid
    int m0 = blockIdx.x * 128;
    int n0 = blockIdx.y * 128;

    uint32_t lm_row = (uint32_t)((lane & 15) * RS + (lane >> 4) * 16);

    float acc[2][4][4];
    #pragma unroll
    for (int i = 0; i < 2; i++)
        #pragma unroll
        for (int j = 0; j < 4; j++)
            #pragma unroll
            for (int q = 0; q < 4; q++) acc[i][j][q] = 0.f;

    load_chunk(base, 0, m0, n0, tid);
    load_chunk(base + BUFB, 1, m0, n0, tid);

    for (int c = 0; c < 4; c++) {
        if (c < 3) asm volatile("cp.async.wait_group 1;" ::: "memory");
        else       asm volatile("cp.async.wait_group 0;" ::: "memory");
        __syncthreads();

        uint32_t buf = base + (uint32_t)(c & 1) * BUFB;
        uint32_t abase = buf + (uint32_t)(wm * 32) * RS + lm_row;
        uint32_t bbase = buf + 2 * TILEB + (uint32_t)(wn * 32) * RS + lm_row;

        #pragma unroll
        for (int ks = 0; ks < 4; ks++) {
            uint32_t koff = (uint32_t)(ks * 32);
            uint32_t ah[2][4], al[2][4], bh[2][4], bl[2][4];
            #pragma unroll
            for (int mi = 0; mi < 2; mi++) {
                ldsm4(ah[mi], abase + (uint32_t)(mi * 16) * RS + koff);
                ldsm4(al[mi], abase + TILEB + (uint32_t)(mi * 16) * RS + koff);
            }
            #pragma unroll
            for (int nt = 0; nt < 2; nt++) {
                ldsm4(bh[nt], bbase + (uint32_t)(nt * 16) * RS + koff);
                ldsm4(bl[nt], bbase + TILEB + (uint32_t)(nt * 16) * RS + koff);
            }
            #pragma unroll
            for (int mi = 0; mi < 2; mi++)
                #pragma unroll
                for (int ni = 0; ni < 4; ni++) {
                    int nt = ni >> 1, sel = ni & 1;
                    uint32_t bbh[2] = { bh[nt][sel], bh[nt][sel + 2] };
                    uint32_t bbl[2] = { bl[nt][sel], bl[nt][sel + 2] };
                    mma16816(acc[mi][ni], ah[mi], bbh);
                    mma16816(acc[mi][ni], ah[mi], bbl);
                    mma16816(acc[mi][ni], al[mi], bbh);
                }
        }
        __syncthreads();
        if (c + 2 <= 3) load_chunk(buf, c + 2, m0, n0, tid);
    }

    // ---- epilogue: ys = dinv[row] * acc
    #pragma unroll
    for (int mi = 0; mi < 2; mi++) {
        int r = m0 + wm * 32 + mi * 16 + g;
        float d0 = g_dinv[r];
        float d1 = g_dinv[r + 8];
        #pragma unroll
        for (int ni = 0; ni < 4; ni++) {
            int ncol = n0 + wn * 32 + ni * 8 + tg * 2;
            float2 o0 = { acc[mi][ni][0] * d0, acc[mi][ni][1] * d0 };
            float2 o1 = { acc[mi][ni][2] * d1, acc[mi][ni][3] * d1 };
            *(float2*)&g_ys[r * CH + ncol]       = o0;
            *(float2*)&g_ys[(r + 8) * CH + ncol] = o1;
        }
    }
}

// ================================================================ aggregate: out = dinv*(Σ_N ys + ys_self) + bias
__global__ void __launch_bounds__(128) k_aggregate(const float* __restrict__ bias,
                                                   float* __restrict__ out)
{
    __shared__ int s_list[CSRW];

    int row   = blockIdx.x;
    int gbase = row & ~(NNODE - 1);
    int t     = threadIdx.x;

    if (t < CSRW) s_list[t] = g_csr[row * CSRW + t];
    __syncthreads();

    int   cnt  = g_cnt[row];
    float dinv = g_dinv[row];
    const float2* ys2 = (const float2*)g_ys;

    float2 a0 = ys2[row * 128 + t];                 // self (eye) term
    float2 a1 = make_float2(0.f, 0.f);
    float2 a2 = make_float2(0.f, 0.f);
    float2 a3 = make_float2(0.f, 0.f);

    int p = 0;
    for (; p + 4 <= cnt; p += 4) {
        int j0 = gbase + s_list[p];
        int j1 = gbase + s_list[p + 1];
        int j2 = gbase + s_list[p + 2];
        int j3 = gbase + s_list[p + 3];
        float2 v0 = ys2[j0 * 128 + t];
        float2 v1 = ys2[j1 * 128 + t];
        float2 v2 = ys2[j2 * 128 + t];
        float2 v3 = ys2[j3 * 128 + t];
        a0.x += v0.x; a0.y += v0.y;
        a1.x += v1.x; a1.y += v1.y;
        a2.x += v2.x; a2.y += v2.y;
        a3.x += v3.x; a3.y += v3.y;
    }
    for (; p < cnt; p++) {
        int j = gbase + s_list[p];
        float2 v = ys2[j * 128 + t];
        a0.x += v.x; a0.y += v.y;
    }
    a0.x += a1.x + a2.x + a3.x;
    a0.y += a1.y + a2.y + a3.y;

    float2 bv = *(const float2*)&bias[t * 2];
    float2 o;
    o.x = dinv * a0.x + bv.x;
    o.y = dinv * a0.y + bv.y;
    *(float2*)&out[row * CH + t * 2] = o;
}

// ================================================================ launch
extern "C" void kernel_launch(void* const* d_in, const int* in_sizes, int n_in,
                              void* d_out, int out_size)
{
    const float* x    = (const float*)d_in[0];   // [8,1024,256] f32
    const int*   ei   = (const int*)  d_in[1];   // [2,16384,8] int32
    const float* Wm   = (const float*)d_in[2];   // [256,256] f32
    const float* bias = (const float*)d_in[3];   // [256] f32
    float*       out  = (float*)d_out;

    cudaFuncSetAttribute(k_gemm, cudaFuncAttributeMaxDynamicSharedMemorySize, GSM);

    k_prep<<<BIGN * CH / 4 / 256, 256>>>(x, Wm);
    k_scatter<<<(NEDGE * BATCH + 255) / 256, 256>>>(ei);
    k_deg<<<BIGN / 8, 256>>>();
    k_gemm<<<dim3(BIGN / 128, CH / 128), 512, GSM>>>();
    k_aggregate<<<BIGN, 128>>>(bias, out);
}

// round 8
// speedup vs baseline: 1.1159x; 1.1159x over previous
#include <cuda_runtime.h>
#include <cuda_bf16.h>
#include <stdint.h>

#define BATCH   8
#define NNODE   1024
#define CH      256
#define NEDGE   16384
#define BIGN    (BATCH * NNODE)          // 8192
#define WPR     32                       // bitmap words per row
#define CSRW    48                       // padded CSR width per row (ints)

// ---- scratch (__device__ globals; allocation-free rule) ----
__device__ __align__(128) unsigned g_adj[BIGN * WPR];    // 1 MB adjacency bitmap
__device__ __align__(128) float    g_dinv[BIGN];
__device__ __align__(128) float    g_ys[BIGN * CH];      // ys = dinv * (x @ W^T)
__device__ __align__(128) int      g_csr[BIGN * CSRW];
__device__ __align__(128) int      g_cnt[BIGN];
// packed bf16 hi/lo tiles, SW128-swizzled, contiguous per (tile, kchunk):
// x: [64 m-tiles][4 chunks][hi 16KB | lo 16KB]   w: [2 n-halves][4 chunks][hi|lo]
__device__ __align__(128) char     g_xpk[64 * 4 * 32768];   // 8 MB
__device__ __align__(128) char     g_wpk[2 * 4 * 32768];    // 256 KB

// ================================================================ helpers
__device__ __forceinline__ uint32_t s2u(const void* p) {
    uint32_t a;
    asm("{ .reg .u64 t; cvta.to.shared.u64 t, %1; cvt.u32.u64 %0, t; }" : "=r"(a) : "l"(p));
    return a;
}
__device__ __forceinline__ void split2(float2 f, uint32_t& hi, uint32_t& lo) {
    asm("cvt.rn.bf16x2.f32 %0, %1, %2;" : "=r"(hi) : "f"(f.y), "f"(f.x));
    float hx = __uint_as_float(hi << 16);
    float hy = __uint_as_float(hi & 0xffff0000u);
    asm("cvt.rn.bf16x2.f32 %0, %1, %2;" : "=r"(lo) : "f"(f.y - hy), "f"(f.x - hx));
}
__device__ __forceinline__ void mma16816(float* c, const uint32_t* a, const uint32_t* b) {
    asm volatile(
        "mma.sync.aligned.m16n8k16.row.col.f32.bf16.bf16.f32 "
        "{%0,%1,%2,%3}, {%4,%5,%6,%7}, {%8,%9}, {%0,%1,%2,%3};"
        : "+f"(c[0]), "+f"(c[1]), "+f"(c[2]), "+f"(c[3])
        : "r"(a[0]), "r"(a[1]), "r"(a[2]), "r"(a[3]), "r"(b[0]), "r"(b[1]));
}
__device__ __forceinline__ void ldsm4(uint32_t* r, uint32_t addr) {
    asm volatile("ldmatrix.sync.aligned.m8n8.x4.shared.b16 {%0,%1,%2,%3}, [%4];"
                 : "=r"(r[0]), "=r"(r[1]), "=r"(r[2]), "=r"(r[3]) : "r"(addr));
}
__device__ __forceinline__ void mbar_wait(uint32_t addr, uint32_t parity) {
    asm volatile(
        "{\n\t.reg .pred P1;\n"
        "WL%=:\n\t"
        "mbarrier.try_wait.parity.acquire.cta.shared::cta.b64 P1, [%0], %1, 0x989680;\n\t"
        "@P1 bra WD%=;\n\t"
        "bra WL%=;\n"
        "WD%=:\n\t}"
        :: "r"(addr), "r"(parity) : "memory");
}
__device__ __forceinline__ void bulk_cp(uint32_t sdst, const void* gsrc, uint32_t bytes,
                                        uint32_t mb) {
    asm volatile(
        "{ .reg .u64 g; cvta.to.global.u64 g, %1;\n\t"
        "cp.async.bulk.shared::cta.global.mbarrier::complete_tx::bytes [%0], [g], %2, [%3]; }"
        :: "r"(sdst), "l"(gsrc), "r"(bytes), "r"(mb) : "memory");
}

// ================================================================ prep: pack x,W as swizzled bf16 hi/lo chunk tiles + zero bitmap
__global__ void __launch_bounds__(256) k_prep(const float* __restrict__ x,
                                              const float* __restrict__ Wm)
{
    int t = blockIdx.x * 256 + threadIdx.x;        // 524288; one float4 of x each
    float4 v = ((const float4*)x)[t];
    uint32_t h0, l0, h1, l1;
    split2(make_float2(v.x, v.y), h0, l0);
    split2(make_float2(v.z, v.w), h1, l1);
    {
        int row = t >> 6, col4 = (t & 63) * 4;
        int tile = row >> 7, r = row & 127, c = col4 >> 6, cc = col4 & 63;
        uint32_t off = (uint32_t)((tile * 4 + c) * 32768)
                     + ((uint32_t)(r * 128 + cc * 2) ^ ((uint32_t)(r & 7) << 4));
        *(uint2*)(g_xpk + off)         = make_uint2(h0, h1);
        *(uint2*)(g_xpk + off + 16384) = make_uint2(l0, l1);
    }
    if (t < CH * CH / 4) {
        float4 w = ((const float4*)Wm)[t];
        split2(make_float2(w.x, w.y), h0, l0);
        split2(make_float2(w.z, w.w), h1, l1);
        int row = t >> 6, col4 = (t & 63) * 4;
        int hf = row >> 7, r = row & 127, c = col4 >> 6, cc = col4 & 63;
        uint32_t off = (uint32_t)((hf * 4 + c) * 32768)
                     + ((uint32_t)(r * 128 + cc * 2) ^ ((uint32_t)(r & 7) << 4));
        *(uint2*)(g_wpk + off)         = make_uint2(h0, h1);
        *(uint2*)(g_wpk + off + 16384) = make_uint2(l0, l1);
    }
    if (t < BIGN * WPR / 4)
        ((uint4*)g_adj)[t] = make_uint4(0u, 0u, 0u, 0u);
}

// ================================================================ edge scatter (dedup via bitmap)
__global__ void k_scatter(const int* __restrict__ ei) {
    int t = blockIdx.x * blockDim.x + threadIdx.x;
    if (t >= NEDGE * BATCH) return;
    int src = ei[t];
    int dst = ei[NEDGE * BATCH + t];
    int b   = t & (BATCH - 1);
    int row = b * NNODE + src;
    atomicOr(&g_adj[row * WPR + (dst >> 5)], 1u << (dst & 31));
}

// ================================================================ degree -> dinv + CSR extraction
__global__ void __launch_bounds__(256) k_deg() {
    int tid  = threadIdx.x;
    int lane = tid & 31;
    int r    = blockIdx.x * 8 + (tid >> 5);

    unsigned w = g_adj[r * WPR + lane];
    int c = __popc(w);
    int s = c;
    #pragma unroll
    for (int o = 1; o < 32; o <<= 1) {
        int v = __shfl_up_sync(0xffffffffu, s, o);
        if (lane >= o) s += v;
    }
    int excl  = s - c;
    int total = __shfl_sync(0xffffffffu, s, 31);
    if (lane == 0) {
        g_dinv[r] = rsqrtf((float)(total + 1));    // +1 self loop (eye)
        g_cnt[r]  = total;
    }
    int i = 0;
    while (w) {
        int b = __ffs(w) - 1;
        w &= w - 1;
        if (excl + i < CSRW) g_csr[r * CSRW + excl + i] = lane * 32 + b;
        i++;
    }
}

// ================================================================ bulk-copy pipelined HMMA GEMM: ys = dinv * (x @ W^T)
// CTA 128x128 (mt, half), 512 threads (16 warps 4x4), warp tile 32x32.
// K chunks of 64 staged by cp.async.bulk (2 x 32KB per chunk), double buffered.
#define GSM 131072

__device__ __forceinline__ void issue_chunk(uint32_t sbuf, uint32_t mb, int mt, int hf, int c) {
    asm volatile("mbarrier.arrive.expect_tx.shared.b64 _, [%0], %1;"
                 :: "r"(mb), "r"(65536u) : "memory");
    bulk_cp(sbuf,          g_xpk + (mt * 4 + c) * 32768, 32768u, mb);
    bulk_cp(sbuf + 32768u, g_wpk + (hf * 4 + c) * 32768, 32768u, mb);
}

__global__ void __launch_bounds__(512) k_gemm()
{
    extern __shared__ __align__(128) char dsm[];
    __shared__ __align__(8) unsigned long long s_mbar[2];
    uint32_t base = s2u(dsm);
    uint32_t mbar = s2u(s_mbar);

    int tid = threadIdx.x;
    int wid = tid >> 5, lane = tid & 31;
    int g = lane >> 2, tg = lane & 3;
    int wm = wid >> 2, wn = wid & 3;
    int mt = blockIdx.x, hf = blockIdx.y;

    if (tid == 0) {
        asm volatile("mbarrier.init.shared.b64 [%0], 1;" :: "r"(mbar)     : "memory");
        asm volatile("mbarrier.init.shared.b64 [%0], 1;" :: "r"(mbar + 8) : "memory");
    }
    __syncthreads();
    if (tid == 0) {
        issue_chunk(base,          mbar,     mt, hf, 0);
        issue_chunk(base + 65536u, mbar + 8, mt, hf, 1);
    }

    uint32_t lanerow = (uint32_t)((lane & 15) * 128);
    uint32_t colbase = (uint32_t)((lane >> 4) * 16);
    uint32_t xorm    = (uint32_t)((lane & 7) << 4);

    float acc[2][4][4];
    #pragma unroll
    for (int i = 0; i < 2; i++)
        #pragma unroll
        for (int j = 0; j < 4; j++)
            #pragma unroll
            for (int q = 0; q < 4; q++) acc[i][j][q] = 0.f;

    for (int c = 0; c < 4; c++) {
        uint32_t buf = base + (uint32_t)(c & 1) * 65536u;
        mbar_wait(mbar + (uint32_t)(c & 1) * 8, (uint32_t)(c >> 1));

        uint32_t abase = buf + (uint32_t)(wm * 32 * 128) + lanerow;           // hi; lo at +16384
        uint32_t bbase = buf + 32768u + (uint32_t)(wn * 32 * 128) + lanerow;

        #pragma unroll
        for (int ks = 0; ks < 4; ks++) {
            uint32_t koff = (colbase + (uint32_t)(ks * 32)) ^ xorm;
            uint32_t ah[2][4], al[2][4], bh[2][4], bl[2][4];
            #pragma unroll
            for (int mi = 0; mi < 2; mi++) {
                ldsm4(ah[mi], abase + (uint32_t)(mi * 2048) + koff);
                ldsm4(al[mi], abase + 16384u + (uint32_t)(mi * 2048) + koff);
            }
            #pragma unroll
            for (int nt = 0; nt < 2; nt++) {
                ldsm4(bh[nt], bbase + (uint32_t)(nt * 2048) + koff);
                ldsm4(bl[nt], bbase + 16384u + (uint32_t)(nt * 2048) + koff);
            }
            #pragma unroll
            for (int mi = 0; mi < 2; mi++)
                #pragma unroll
                for (int ni = 0; ni < 4; ni++) {
                    int nt = ni >> 1, sel = ni & 1;
                    uint32_t bbh[2] = { bh[nt][sel], bh[nt][sel + 2] };
                    uint32_t bbl[2] = { bl[nt][sel], bl[nt][sel + 2] };
                    mma16816(acc[mi][ni], ah[mi], bbh);
                    mma16816(acc[mi][ni], ah[mi], bbl);
                    mma16816(acc[mi][ni], al[mi], bbh);
                }
        }
        __syncthreads();                       // all warps done with this buffer
        if (c < 2 && tid == 0)
            issue_chunk(buf, mbar + (uint32_t)(c & 1) * 8, mt, hf, c + 2);
    }

    // ---- epilogue: ys = dinv[row] * acc
    int m0 = mt * 128, n0 = hf * 128;
    #pragma unroll
    for (int mi = 0; mi < 2; mi++) {
        int r = m0 + wm * 32 + mi * 16 + g;
        float d0 = g_dinv[r];
        float d1 = g_dinv[r + 8];
        #pragma unroll
        for (int ni = 0; ni < 4; ni++) {
            int ncol = n0 + wn * 32 + ni * 8 + tg * 2;
            float2 o0 = { acc[mi][ni][0] * d0, acc[mi][ni][1] * d0 };
            float2 o1 = { acc[mi][ni][2] * d1, acc[mi][ni][3] * d1 };
            *(float2*)&g_ys[r * CH + ncol]       = o0;
            *(float2*)&g_ys[(r + 8) * CH + ncol] = o1;
        }
    }
}

// ================================================================ aggregate: out = dinv*(Σ_N ys + ys_self) + bias
__global__ void __launch_bounds__(128) k_aggregate(const float* __restrict__ bias,
                                                   float* __restrict__ out)
{
    __shared__ int s_list[CSRW];

    int row   = blockIdx.x;
    int gbase = row & ~(NNODE - 1);
    int t     = threadIdx.x;

    if (t < CSRW) s_list[t] = g_csr[row * CSRW + t];
    __syncthreads();

    int   cnt  = g_cnt[row];
    float dinv = g_dinv[row];
    const float2* ys2 = (const float2*)g_ys;

    float2 a0 = ys2[row * 128 + t];                 // self (eye) term
    float2 a1 = make_float2(0.f, 0.f);
    float2 a2 = make_float2(0.f, 0.f);
    float2 a3 = make_float2(0.f, 0.f);

    int p = 0;
    for (; p + 4 <= cnt; p += 4) {
        int j0 = gbase + s_list[p];
        int j1 = gbase + s_list[p + 1];
        int j2 = gbase + s_list[p + 2];
        int j3 = gbase + s_list[p + 3];
        float2 v0 = ys2[j0 * 128 + t];
        float2 v1 = ys2[j1 * 128 + t];
        float2 v2 = ys2[j2 * 128 + t];
        float2 v3 = ys2[j3 * 128 + t];
        a0.x += v0.x; a0.y += v0.y;
        a1.x += v1.x; a1.y += v1.y;
        a2.x += v2.x; a2.y += v2.y;
        a3.x += v3.x; a3.y += v3.y;
    }
    for (; p < cnt; p++) {
        int j = gbase + s_list[p];
        float2 v = ys2[j * 128 + t];
        a0.x += v.x; a0.y += v.y;
    }
    a0.x += a1.x + a2.x + a3.x;
    a0.y += a1.y + a2.y + a3.y;

    float2 bv = *(const float2*)&bias[t * 2];
    float2 o;
    o.x = dinv * a0.x + bv.x;
    o.y = dinv * a0.y + bv.y;
    *(float2*)&out[row * CH + t * 2] = o;
}

// ================================================================ launch
extern "C" void kernel_launch(void* const* d_in, const int* in_sizes, int n_in,
                              void* d_out, int out_size)
{
    const float* x    = (const float*)d_in[0];   // [8,1024,256] f32
    const int*   ei   = (const int*)  d_in[1];   // [2,16384,8] int32
    const float* Wm   = (const float*)d_in[2];   // [256,256] f32
    const float* bias = (const float*)d_in[3];   // [256] f32
    float*       out  = (float*)d_out;

    cudaFuncSetAttribute(k_gemm, cudaFuncAttributeMaxDynamicSharedMemorySize, GSM);

    k_prep<<<BIGN * CH / 4 / 256, 256>>>(x, Wm);
    k_scatter<<<(NEDGE * BATCH + 255) / 256, 256>>>(ei);
    k_deg<<<BIGN / 8, 256>>>();
    k_gemm<<<dim3(BIGN / 128, CH / 128), 512, GSM>>>();
    k_aggregate<<<BIGN, 128>>>(bias, out);
}